// round 1
// baseline (speedup 1.0000x reference)
#include <cuda_runtime.h>
#include <math.h>

// ---------------------------------------------------------------------------
// FEMRMamba: 2-layer Mamba over 8 ragged subjects, compact [6848] token layout
// ---------------------------------------------------------------------------

#define TOTAL   6848
#define DM      768
#define DI      1536
#define DS      16
#define DTRANK  48
#define NSUBJ   8
#define EPS     1e-5f

__constant__ int c_off[NSUBJ] = {0, 1024, 1920, 2688, 3712, 4224, 4864, 5824};
__constant__ int c_len[NSUBJ] = {1024, 896, 768, 1024, 512, 640, 960, 1024};

// scratch (device globals: allocation-free rule)
__device__ float g_x  [TOTAL * DM];       // residual stream h
__device__ float g_hn [TOTAL * DM];       // rmsnorm(h)
__device__ float g_xz [TOTAL * 2 * DI];   // in_proj out (x | z)
__device__ float g_xs [TOTAL * DI];       // silu(conv(x))
__device__ float g_dbl[TOTAL * 80];       // x_proj out (dt48 | B16 | C16)
__device__ float g_dtp[TOTAL * DI];       // dt_proj out (pre-softplus, pre-bias)
__device__ float g_y  [TOTAL * DI];       // scan output (gated)

__device__ __forceinline__ float warp_sum(float v) {
#pragma unroll
    for (int o = 16; o > 0; o >>= 1) v += __shfl_xor_sync(0xffffffffu, v, o);
    return v;
}

// ---------------------------------------------------------------------------
// embed gather + rmsnorm(in_norm_w). warp per row.
// ---------------------------------------------------------------------------
__global__ void k_embed(const int* __restrict__ tokens,
                        const float* __restrict__ embed,
                        const float* __restrict__ w,
                        float* __restrict__ out) {
    int row  = blockIdx.x * 8 + (threadIdx.x >> 5);
    int lane = threadIdx.x & 31;
    if (row >= TOTAL) return;
    int tok = tokens[row];
    const float4* e  = (const float4*)(embed + (size_t)tok * DM);
    const float4* w4 = (const float4*)w;
    float4 v[6];
    float ss = 0.f;
#pragma unroll
    for (int i = 0; i < 6; i++) {
        v[i] = e[lane + 32 * i];
        ss += v[i].x * v[i].x + v[i].y * v[i].y + v[i].z * v[i].z + v[i].w * v[i].w;
    }
    ss = warp_sum(ss);
    float r = rsqrtf(ss * (1.f / DM) + EPS);
    float4* o4 = (float4*)(out + (size_t)row * DM);
#pragma unroll
    for (int i = 0; i < 6; i++) {
        float4 wv = w4[lane + 32 * i];
        float4 t;
        t.x = v[i].x * r * wv.x; t.y = v[i].y * r * wv.y;
        t.z = v[i].z * r * wv.z; t.w = v[i].w * r * wv.w;
        o4[lane + 32 * i] = t;
    }
}

// ---------------------------------------------------------------------------
// per-row rmsnorm. warp per row.
// ---------------------------------------------------------------------------
__global__ void k_rmsnorm(const float* __restrict__ in,
                          const float* __restrict__ w,
                          float* __restrict__ out) {
    int row  = blockIdx.x * 8 + (threadIdx.x >> 5);
    int lane = threadIdx.x & 31;
    if (row >= TOTAL) return;
    const float4* p  = (const float4*)(in + (size_t)row * DM);
    const float4* w4 = (const float4*)w;
    float4 v[6];
    float ss = 0.f;
#pragma unroll
    for (int i = 0; i < 6; i++) {
        v[i] = p[lane + 32 * i];
        ss += v[i].x * v[i].x + v[i].y * v[i].y + v[i].z * v[i].z + v[i].w * v[i].w;
    }
    ss = warp_sum(ss);
    float r = rsqrtf(ss * (1.f / DM) + EPS);
    float4* o4 = (float4*)(out + (size_t)row * DM);
#pragma unroll
    for (int i = 0; i < 6; i++) {
        float4 wv = w4[lane + 32 * i];
        float4 t;
        t.x = v[i].x * r * wv.x; t.y = v[i].y * r * wv.y;
        t.z = v[i].z * r * wv.z; t.w = v[i].w * r * wv.w;
        o4[lane + 32 * i] = t;
    }
}

// ---------------------------------------------------------------------------
// SGEMM NT: C[m,n] = sum_k A[m,k]*B[n,k]  (+ optional residual add in-place)
// 128x128x8 tiles, 256 threads, 8x8 per thread.
// ---------------------------------------------------------------------------
#define BM 128
#define BN 128
#define BK 8
#define TM 8
#define TN 8

__global__ __launch_bounds__(256) void k_sgemm_nt(
    const float* __restrict__ A, int lda,
    const float* __restrict__ B, int ldb,
    float* __restrict__ C, int ldc,
    int M, int N, int K, int addResidual) {
    __shared__ float As[BK][BM];
    __shared__ float Bs[BK][BN];
    int tid = threadIdx.x;
    int bm = blockIdx.y * BM;
    int bn = blockIdx.x * BN;
    int lr = tid >> 1;           // 0..127 row within tile (load)
    int lc = (tid & 1) * 4;      // 0 or 4 (k offset, float4)
    int tx = tid & 15, ty = tid >> 4;

    float acc[TM][TN];
#pragma unroll
    for (int i = 0; i < TM; i++)
#pragma unroll
        for (int j = 0; j < TN; j++) acc[i][j] = 0.f;

    for (int k0 = 0; k0 < K; k0 += BK) {
        float4 av = make_float4(0.f, 0.f, 0.f, 0.f);
        int am = bm + lr;
        if (am < M) av = *(const float4*)(A + (size_t)am * lda + k0 + lc);
        As[lc + 0][lr] = av.x; As[lc + 1][lr] = av.y;
        As[lc + 2][lr] = av.z; As[lc + 3][lr] = av.w;

        float4 bv = make_float4(0.f, 0.f, 0.f, 0.f);
        int bnr = bn + lr;
        if (bnr < N) bv = *(const float4*)(B + (size_t)bnr * ldb + k0 + lc);
        Bs[lc + 0][lr] = bv.x; Bs[lc + 1][lr] = bv.y;
        Bs[lc + 2][lr] = bv.z; Bs[lc + 3][lr] = bv.w;
        __syncthreads();

#pragma unroll
        for (int k = 0; k < BK; k++) {
            float af[TM], bf[TN];
            *(float4*)&af[0] = *(const float4*)&As[k][ty * TM];
            *(float4*)&af[4] = *(const float4*)&As[k][ty * TM + 4];
            *(float4*)&bf[0] = *(const float4*)&Bs[k][tx * TN];
            *(float4*)&bf[4] = *(const float4*)&Bs[k][tx * TN + 4];
#pragma unroll
            for (int i = 0; i < TM; i++)
#pragma unroll
                for (int j = 0; j < TN; j++)
                    acc[i][j] = fmaf(af[i], bf[j], acc[i][j]);
        }
        __syncthreads();
    }

#pragma unroll
    for (int i = 0; i < TM; i++) {
        int m = bm + ty * TM + i;
        if (m >= M) continue;
#pragma unroll
        for (int j = 0; j < TN; j += 4) {
            int n = bn + tx * TN + j;
            if (n + 3 < N) {
                float4 v = make_float4(acc[i][j], acc[i][j + 1], acc[i][j + 2], acc[i][j + 3]);
                if (addResidual) {
                    float4 r = *(float4*)(C + (size_t)m * ldc + n);
                    v.x += r.x; v.y += r.y; v.z += r.z; v.w += r.w;
                }
                *(float4*)(C + (size_t)m * ldc + n) = v;
            } else {
                for (int jj = 0; jj < 4; jj++) {
                    if (n + jj < N) {
                        float v = acc[i][j + jj];
                        if (addResidual) v += C[(size_t)m * ldc + n + jj];
                        C[(size_t)m * ldc + n + jj] = v;
                    }
                }
            }
        }
    }
}

// ---------------------------------------------------------------------------
// causal depthwise conv (K=4) + bias + silu, on x half of xz
// ---------------------------------------------------------------------------
__global__ void k_conv(const float* __restrict__ xz,
                       const float* __restrict__ cw,
                       const float* __restrict__ cb,
                       float* __restrict__ xs) {
    int idx = blockIdx.x * blockDim.x + threadIdx.x;
    if (idx >= TOTAL * DI) return;
    int row = idx / DI;
    int d = idx - row * DI;
    int b = 0;
#pragma unroll
    for (int i = 1; i < NSUBJ; i++) if (row >= c_off[i]) b = i;
    int l = row - c_off[b];
    float acc = cb[d];
#pragma unroll
    for (int j = 0; j < 4; j++) {
        int ll = l - 3 + j;
        if (ll >= 0)
            acc = fmaf(cw[d * 4 + j], xz[(size_t)(row - 3 + j) * (2 * DI) + d], acc);
    }
    xs[idx] = acc / (1.f + __expf(-acc));   // silu
}

// ---------------------------------------------------------------------------
// selective scan: one thread per (subject, d-channel), 16 states in regs.
// Fuses softplus(dt_proj + bias), the recurrence, +x*D, and *silu(z).
// ---------------------------------------------------------------------------
__global__ __launch_bounds__(128) void k_scan(
    const float* __restrict__ dtp, const float* __restrict__ xs,
    const float* __restrict__ dbl, const float* __restrict__ xz,
    float* __restrict__ yb,
    const float* __restrict__ dtb, const float* __restrict__ alog,
    const float* __restrict__ Dp) {
    int s = blockIdx.x / (DI / 128);
    int d = (blockIdx.x % (DI / 128)) * 128 + threadIdx.x;
    int off = c_off[s], len = c_len[s];

    float a[DS], st[DS];
#pragma unroll
    for (int n = 0; n < DS; n++) {
        a[n] = -expf(alog[d * DS + n]);
        st[n] = 0.f;
    }
    float bias = dtb[d], Dd = Dp[d];

    for (int t = 0; t < len; t++) {
        int row = off + t;
        float dtr = dtp[(size_t)row * DI + d] + bias;
        float dt = (dtr > 20.f) ? dtr : log1pf(__expf(dtr));
        float xt = xs[(size_t)row * DI + d];
        const float4* bc = (const float4*)(dbl + (size_t)row * 80 + DTRANK);
        float Bv[DS], Cv[DS];
        *(float4*)&Bv[0]  = bc[0]; *(float4*)&Bv[4]  = bc[1];
        *(float4*)&Bv[8]  = bc[2]; *(float4*)&Bv[12] = bc[3];
        *(float4*)&Cv[0]  = bc[4]; *(float4*)&Cv[4]  = bc[5];
        *(float4*)&Cv[8]  = bc[6]; *(float4*)&Cv[12] = bc[7];
        float u = dt * xt;
        float y = 0.f;
#pragma unroll
        for (int n = 0; n < DS; n++) {
            float dA = __expf(dt * a[n]);
            st[n] = fmaf(dA, st[n], u * Bv[n]);
            y = fmaf(st[n], Cv[n], y);
        }
        float z = xz[(size_t)row * (2 * DI) + DI + d];
        float sig = 1.f / (1.f + __expf(-z));
        yb[(size_t)row * DI + d] = (y + xt * Dd) * (z * sig);
    }
}

// ---------------------------------------------------------------------------
// final: rmsnorm(norm_f_w) then rmsnorm(out_norm_w), write to d_out
// ---------------------------------------------------------------------------
__global__ void k_final(const float* __restrict__ h,
                        const float* __restrict__ wf,
                        const float* __restrict__ wo,
                        float* __restrict__ out) {
    int row  = blockIdx.x * 8 + (threadIdx.x >> 5);
    int lane = threadIdx.x & 31;
    if (row >= TOTAL) return;
    const float4* p   = (const float4*)(h + (size_t)row * DM);
    const float4* wf4 = (const float4*)wf;
    const float4* wo4 = (const float4*)wo;
    float4 v[6];
    float ss = 0.f;
#pragma unroll
    for (int i = 0; i < 6; i++) {
        v[i] = p[lane + 32 * i];
        ss += v[i].x * v[i].x + v[i].y * v[i].y + v[i].z * v[i].z + v[i].w * v[i].w;
    }
    ss = warp_sum(ss);
    float r1 = rsqrtf(ss * (1.f / DM) + EPS);
    float ss2 = 0.f;
#pragma unroll
    for (int i = 0; i < 6; i++) {
        float4 wv = wf4[lane + 32 * i];
        v[i].x *= r1 * wv.x; v[i].y *= r1 * wv.y;
        v[i].z *= r1 * wv.z; v[i].w *= r1 * wv.w;
        ss2 += v[i].x * v[i].x + v[i].y * v[i].y + v[i].z * v[i].z + v[i].w * v[i].w;
    }
    ss2 = warp_sum(ss2);
    float r2 = rsqrtf(ss2 * (1.f / DM) + EPS);
    float4* o4 = (float4*)(out + (size_t)row * DM);
#pragma unroll
    for (int i = 0; i < 6; i++) {
        float4 wv = wo4[lane + 32 * i];
        float4 t;
        t.x = v[i].x * r2 * wv.x; t.y = v[i].y * r2 * wv.y;
        t.z = v[i].z * r2 * wv.z; t.w = v[i].w * r2 * wv.w;
        o4[lane + 32 * i] = t;
    }
}

// ---------------------------------------------------------------------------
extern "C" void kernel_launch(void* const* d_in, const int* in_sizes, int n_in,
                              void* d_out, int out_size) {
    const int*   tokens     = (const int*)d_in[0];
    const float* embed      = (const float*)d_in[1];
    const float* in_norm_w  = (const float*)d_in[2];
    const float* out_norm_w = (const float*)d_in[3];
    const float* norm_w     = (const float*)d_in[4];
    const float* in_proj_w  = (const float*)d_in[5];
    const float* conv_w     = (const float*)d_in[6];
    const float* conv_b     = (const float*)d_in[7];
    const float* x_proj_w   = (const float*)d_in[8];
    const float* dt_proj_w  = (const float*)d_in[9];
    const float* dt_proj_b  = (const float*)d_in[10];
    const float* A_log      = (const float*)d_in[11];
    const float* D_param    = (const float*)d_in[12];
    const float* out_proj_w = (const float*)d_in[13];
    const float* norm_f_w   = (const float*)d_in[14];
    float* out = (float*)d_out;

    float *p_x, *p_hn, *p_xz, *p_xs, *p_dbl, *p_dtp, *p_y;
    cudaGetSymbolAddress((void**)&p_x,   g_x);
    cudaGetSymbolAddress((void**)&p_hn,  g_hn);
    cudaGetSymbolAddress((void**)&p_xz,  g_xz);
    cudaGetSymbolAddress((void**)&p_xs,  g_xs);
    cudaGetSymbolAddress((void**)&p_dbl, g_dbl);
    cudaGetSymbolAddress((void**)&p_dtp, g_dtp);
    cudaGetSymbolAddress((void**)&p_y,   g_y);

    const int rowBlocks = (TOTAL + 7) / 8;   // warp-per-row kernels
    const int gy = (TOTAL + BM - 1) / BM;    // 54

    k_embed<<<rowBlocks, 256>>>(tokens, embed, in_norm_w, p_x);

    for (int l = 0; l < 2; l++) {
        const float* ipw = in_proj_w  + (size_t)l * 2 * DI * DM;   // [3072,768]
        const float* cw  = conv_w     + (size_t)l * DI * 4;
        const float* cb  = conv_b     + (size_t)l * DI;
        const float* xpw = x_proj_w   + (size_t)l * 80 * DI;       // [80,1536]
        const float* dpw = dt_proj_w  + (size_t)l * DI * DTRANK;   // [1536,48]
        const float* dpb = dt_proj_b  + (size_t)l * DI;
        const float* al  = A_log      + (size_t)l * DI * DS;
        const float* Dpar= D_param    + (size_t)l * DI;
        const float* opw = out_proj_w + (size_t)l * DM * DI;       // [768,1536]

        k_rmsnorm<<<rowBlocks, 256>>>(p_x, norm_w + (size_t)l * DM, p_hn);

        // xz = hn @ in_proj^T : [TOTAL, 3072]
        k_sgemm_nt<<<dim3(2 * DI / BN, gy), 256>>>(p_hn, DM, ipw, DM,
                                                   p_xz, 2 * DI, TOTAL, 2 * DI, DM, 0);
        // xs = silu(conv(x) + b)
        k_conv<<<(TOTAL * DI + 255) / 256, 256>>>(p_xz, cw, cb, p_xs);

        // dbl = xs @ x_proj^T : [TOTAL, 80]
        k_sgemm_nt<<<dim3(1, gy), 256>>>(p_xs, DI, xpw, DI,
                                         p_dbl, 80, TOTAL, 80, DI, 0);

        // dtp = dbl[:, :48] @ dt_proj^T : [TOTAL, 1536]
        k_sgemm_nt<<<dim3(DI / BN, gy), 256>>>(p_dbl, 80, dpw, DTRANK,
                                               p_dtp, DI, TOTAL, DI, DTRANK, 0);

        // selective scan (fused softplus + gate)
        k_scan<<<NSUBJ * (DI / 128), 128>>>(p_dtp, p_xs, p_dbl, p_xz, p_y,
                                            dpb, al, Dpar);

        // h += y @ out_proj^T : [TOTAL, 768]
        k_sgemm_nt<<<dim3(DM / BN, gy), 256>>>(p_y, DI, opw, DI,
                                               p_x, DM, TOTAL, DM, DI, 1);
    }

    k_final<<<rowBlocks, 256>>>(p_x, norm_f_w, out_norm_w, out);
}

// round 3
// speedup vs baseline: 1.6927x; 1.6927x over previous
#include <cuda_runtime.h>
#include <cuda_bf16.h>
#include <cstdint>
#include <math.h>

// ---------------------------------------------------------------------------
// FEMRMamba: 2-layer Mamba over 8 ragged subjects, compact [6848] layout.
// GEMMs: warp-level HMMA (mma.sync bf16, fp32 acc) with hi/lo split (3-pass).
// ---------------------------------------------------------------------------

#define TOTAL   6848
#define DM      768
#define DI      1536
#define DS      16
#define DTRANK  48
#define NSUBJ   8
#define EPS     1e-5f

__constant__ int c_off[NSUBJ] = {0, 1024, 1920, 2688, 3712, 4224, 4864, 5824};
__constant__ int c_len[NSUBJ] = {1024, 896, 768, 1024, 512, 640, 960, 1024};

// ---------------- scratch (device globals: allocation-free rule) -----------
__device__ float g_x  [TOTAL * DM];        // residual stream h (fp32)
__device__ float g_xz [TOTAL * 2 * DI];    // in_proj out (x | z) fp32
__device__ float g_xs [TOTAL * DI];        // silu(conv(x)) fp32 (scan input)
__device__ float g_dbl[TOTAL * 80];        // x_proj out fp32
__device__ float g_dtp[TOTAL * DI];        // dt_proj out fp32

__device__ __nv_bfloat16 g_hn_hi[TOTAL * DM],  g_hn_lo[TOTAL * DM];
__device__ __nv_bfloat16 g_xs_hi[TOTAL * DI],  g_xs_lo[TOTAL * DI];
__device__ __nv_bfloat16 g_db_hi[TOTAL * 64],  g_db_lo[TOTAL * 64];   // dt48 pad->64
__device__ __nv_bfloat16 g_y_hi [TOTAL * DI],  g_y_lo [TOTAL * DI];
__device__ __nv_bfloat16 g_w_hi [2 * DI * DM], g_w_lo [2 * DI * DM];  // weight buf

// ---------------------------------------------------------------------------
__device__ __forceinline__ float warp_sum(float v) {
#pragma unroll
    for (int o = 16; o > 0; o >>= 1) v += __shfl_xor_sync(0xffffffffu, v, o);
    return v;
}
__device__ __forceinline__ void store_hl(__nv_bfloat16* hi, __nv_bfloat16* lo,
                                         size_t idx, float v) {
    __nv_bfloat16 h = __float2bfloat16(v);
    hi[idx] = h;
    lo[idx] = __float2bfloat16(v - __bfloat162float(h));
}
__device__ __forceinline__ uint32_t smem_u32(const void* p) {
    uint32_t a;
    asm("{ .reg .u64 t; cvta.to.shared.u64 t, %1; cvt.u32.u64 %0, t; }"
        : "=r"(a) : "l"(p));
    return a;
}
__device__ __forceinline__ void cp16(uint32_t dst, const void* src, int srcSize) {
    asm volatile("cp.async.cg.shared.global [%0], [%1], 16, %2;"
                 :: "r"(dst), "l"(src), "r"(srcSize) : "memory");
}
__device__ __forceinline__ void ldsm4(uint32_t& r0, uint32_t& r1, uint32_t& r2,
                                      uint32_t& r3, uint32_t addr) {
    asm volatile("ldmatrix.sync.aligned.m8n8.x4.shared.b16 {%0,%1,%2,%3}, [%4];"
                 : "=r"(r0), "=r"(r1), "=r"(r2), "=r"(r3) : "r"(addr));
}
__device__ __forceinline__ void mma16816(float* c, const uint32_t* a,
                                         const uint32_t* b) {
    asm volatile("mma.sync.aligned.m16n8k16.row.col.f32.bf16.bf16.f32 "
                 "{%0,%1,%2,%3}, {%4,%5,%6,%7}, {%8,%9}, {%0,%1,%2,%3};"
                 : "+f"(c[0]), "+f"(c[1]), "+f"(c[2]), "+f"(c[3])
                 : "r"(a[0]), "r"(a[1]), "r"(a[2]), "r"(a[3]),
                   "r"(b[0]), "r"(b[1]));
}

// ---------------------------------------------------------------------------
// embed gather + rmsnorm(in_norm_w) -> fp32 residual. warp per row.
// ---------------------------------------------------------------------------
__global__ void k_embed(const int* __restrict__ tokens,
                        const float* __restrict__ embed,
                        const float* __restrict__ w,
                        float* __restrict__ out) {
    int row  = blockIdx.x * 8 + (threadIdx.x >> 5);
    int lane = threadIdx.x & 31;
    if (row >= TOTAL) return;
    int tok = tokens[row];
    const float4* e  = (const float4*)(embed + (size_t)tok * DM);
    const float4* w4 = (const float4*)w;
    float4 v[6];
    float ss = 0.f;
#pragma unroll
    for (int i = 0; i < 6; i++) {
        v[i] = e[lane + 32 * i];
        ss += v[i].x * v[i].x + v[i].y * v[i].y + v[i].z * v[i].z + v[i].w * v[i].w;
    }
    ss = warp_sum(ss);
    float r = rsqrtf(ss * (1.f / DM) + EPS);
    float4* o4 = (float4*)(out + (size_t)row * DM);
#pragma unroll
    for (int i = 0; i < 6; i++) {
        float4 wv = w4[lane + 32 * i];
        float4 t;
        t.x = v[i].x * r * wv.x; t.y = v[i].y * r * wv.y;
        t.z = v[i].z * r * wv.z; t.w = v[i].w * r * wv.w;
        o4[lane + 32 * i] = t;
    }
}

// ---------------------------------------------------------------------------
// rmsnorm -> bf16 hi/lo. warp per row.
// ---------------------------------------------------------------------------
__global__ void k_rmsnorm_split(const float* __restrict__ in,
                                const float* __restrict__ w,
                                __nv_bfloat16* __restrict__ hi,
                                __nv_bfloat16* __restrict__ lo) {
    int row  = blockIdx.x * 8 + (threadIdx.x >> 5);
    int lane = threadIdx.x & 31;
    if (row >= TOTAL) return;
    const float4* p  = (const float4*)(in + (size_t)row * DM);
    const float4* w4 = (const float4*)w;
    float4 v[6];
    float ss = 0.f;
#pragma unroll
    for (int i = 0; i < 6; i++) {
        v[i] = p[lane + 32 * i];
        ss += v[i].x * v[i].x + v[i].y * v[i].y + v[i].z * v[i].z + v[i].w * v[i].w;
    }
    ss = warp_sum(ss);
    float r = rsqrtf(ss * (1.f / DM) + EPS);
    size_t base = (size_t)row * DM;
#pragma unroll
    for (int i = 0; i < 6; i++) {
        float4 wv = w4[lane + 32 * i];
        size_t c = base + (lane + 32 * i) * 4;
        store_hl(hi, lo, c + 0, v[i].x * r * wv.x);
        store_hl(hi, lo, c + 1, v[i].y * r * wv.y);
        store_hl(hi, lo, c + 2, v[i].z * r * wv.z);
        store_hl(hi, lo, c + 3, v[i].w * r * wv.w);
    }
}

// ---------------------------------------------------------------------------
// generic fp32 -> bf16 hi/lo split with K padding
// ---------------------------------------------------------------------------
__global__ void k_split(const float* __restrict__ src,
                        __nv_bfloat16* __restrict__ hi,
                        __nv_bfloat16* __restrict__ lo,
                        int rows, int K, int Kpad, int srcLd) {
    int idx = blockIdx.x * blockDim.x + threadIdx.x;
    if (idx >= rows * Kpad) return;
    int r = idx / Kpad, c = idx - r * Kpad;
    float v = (c < K) ? src[(size_t)r * srcLd + c] : 0.f;
    store_hl(hi, lo, idx, v);
}

// ---------------------------------------------------------------------------
// HMMA bf16 GEMM-NT with hi/lo split: C[m,n] = sum_k A[m,k]*B[n,k]
// 3 passes (AhiBhi + AhiBlo + AloBhi) accumulated in fp32 registers.
// Block 128x128xBK32, 256 thr; warp tile 32x64; smem rows padded to 40 halves.
// ---------------------------------------------------------------------------
#define BK 32
#define LDS_ROW 40   // halves per smem row (80B: conflict-free ldmatrix)

__global__ __launch_bounds__(256, 1) void k_gemm(
    const __nv_bfloat16* __restrict__ Ahi, const __nv_bfloat16* __restrict__ Alo,
    const __nv_bfloat16* __restrict__ Bhi, const __nv_bfloat16* __restrict__ Blo,
    float* __restrict__ C, int M, int N, int Kpad, int ldc, int addRes) {
    __shared__ __align__(16) __nv_bfloat16 sA[2][128 * LDS_ROW];
    __shared__ __align__(16) __nv_bfloat16 sB[2][128 * LDS_ROW];

    const int tid = threadIdx.x;
    const int bm = blockIdx.y * 128, bn = blockIdx.x * 128;
    const int wid = tid >> 5, lane = tid & 31;
    const int wm = wid & 3, wn = wid >> 2;

    const int nch = Kpad / BK;
    const int tot = 3 * nch;

    const __nv_bfloat16* Aps[3] = {Ahi, Ahi, Alo};
    const __nv_bfloat16* Bps[3] = {Bhi, Blo, Bhi};

    float acc[2][8][4];
#pragma unroll
    for (int i = 0; i < 2; i++)
#pragma unroll
        for (int j = 0; j < 8; j++)
#pragma unroll
            for (int q = 0; q < 4; q++) acc[i][j][q] = 0.f;

    // loader indices: each thread fills one row-half (32B) of A and B
    const int lrow = tid & 127;
    const int lch = (tid >> 7) * 2;            // chunk 0/1 or 2/3 (16B each)
    const int okA = (bm + lrow) < M ? 16 : 0;
    const int okB = (bn + lrow) < N ? 16 : 0;
    const uint32_t sA0 = smem_u32(&sA[0][0]), sB0 = smem_u32(&sB[0][0]);
    const uint32_t dstA = sA0 + (lrow * LDS_ROW + lch * 8) * 2;
    const uint32_t dstB = sB0 + (lrow * LDS_ROW + lch * 8) * 2;
    const uint32_t bufStride = 128 * LDS_ROW * 2;

#define LOAD_STAGE(it, buf) do {                                               \
    int _p = (it) / nch;                                                       \
    int _kc = ((it) - _p * nch) * BK;                                          \
    const __nv_bfloat16* _Ap = Aps[_p] + (size_t)(bm + lrow) * Kpad + _kc + lch * 8; \
    const __nv_bfloat16* _Bp = Bps[_p] + (size_t)(bn + lrow) * Kpad + _kc + lch * 8; \
    cp16(dstA + (buf) * bufStride,      _Ap,     okA);                         \
    cp16(dstA + (buf) * bufStride + 16, _Ap + 8, okA);                         \
    cp16(dstB + (buf) * bufStride,      _Bp,     okB);                         \
    cp16(dstB + (buf) * bufStride + 16, _Bp + 8, okB);                         \
    asm volatile("cp.async.commit_group;" ::: "memory");                       \
} while (0)

    LOAD_STAGE(0, 0);

    for (int it = 0; it < tot; ++it) {
        int buf = it & 1;
        if (it + 1 < tot) {
            LOAD_STAGE(it + 1, buf ^ 1);
            asm volatile("cp.async.wait_group 1;" ::: "memory");
        } else {
            asm volatile("cp.async.wait_group 0;" ::: "memory");
        }
        __syncthreads();

        const uint32_t aBase = sA0 + buf * bufStride;
        const uint32_t bBase = sB0 + buf * bufStride;
#pragma unroll
        for (int k16 = 0; k16 < 2; ++k16) {
            const int kcol = k16 * 16 + ((lane >> 4) << 3);
            uint32_t afr[2][4];
#pragma unroll
            for (int mt = 0; mt < 2; ++mt) {
                int row = wm * 32 + mt * 16 + (lane & 15);
                ldsm4(afr[mt][0], afr[mt][1], afr[mt][2], afr[mt][3],
                      aBase + (row * LDS_ROW + kcol) * 2);
            }
            uint32_t bfr[4][4];
#pragma unroll
            for (int g = 0; g < 4; ++g) {
                int row = wn * 64 + g * 16 + ((lane >> 4) << 3) + (lane & 7);
                int col = k16 * 16 + (((lane >> 3) & 1) << 3);
                ldsm4(bfr[g][0], bfr[g][1], bfr[g][2], bfr[g][3],
                      bBase + (row * LDS_ROW + col) * 2);
            }
#pragma unroll
            for (int mt = 0; mt < 2; ++mt)
#pragma unroll
                for (int g = 0; g < 4; ++g) {
                    mma16816(acc[mt][2 * g],     afr[mt], &bfr[g][0]);
                    mma16816(acc[mt][2 * g + 1], afr[mt], &bfr[g][2]);
                }
        }
        __syncthreads();
    }

    // epilogue
#pragma unroll
    for (int mt = 0; mt < 2; ++mt) {
#pragma unroll
        for (int h = 0; h < 2; ++h) {
            int m = bm + wm * 32 + mt * 16 + (lane >> 2) + h * 8;
            if (m >= M) continue;
#pragma unroll
            for (int nt = 0; nt < 8; ++nt) {
                int n = bn + wn * 64 + nt * 8 + (lane & 3) * 2;
                if (n < N) {
                    float2 v = make_float2(acc[mt][nt][2 * h], acc[mt][nt][2 * h + 1]);
                    float* cp = C + (size_t)m * ldc + n;
                    if (addRes) { float2 o = *(float2*)cp; v.x += o.x; v.y += o.y; }
                    *(float2*)cp = v;
                }
            }
        }
    }
#undef LOAD_STAGE
}

// ---------------------------------------------------------------------------
// causal depthwise conv (K=4) + bias + silu -> fp32 + bf16 hi/lo
// ---------------------------------------------------------------------------
__global__ void k_conv(const float* __restrict__ xz,
                       const float* __restrict__ cw,
                       const float* __restrict__ cb,
                       float* __restrict__ xs,
                       __nv_bfloat16* __restrict__ xhi,
                       __nv_bfloat16* __restrict__ xlo) {
    int idx = blockIdx.x * blockDim.x + threadIdx.x;
    if (idx >= TOTAL * DI) return;
    int row = idx / DI;
    int d = idx - row * DI;
    int b = 0;
#pragma unroll
    for (int i = 1; i < NSUBJ; i++) if (row >= c_off[i]) b = i;
    int l = row - c_off[b];
    float acc = cb[d];
#pragma unroll
    for (int j = 0; j < 4; j++) {
        int ll = l - 3 + j;
        if (ll >= 0)
            acc = fmaf(cw[d * 4 + j], xz[(size_t)(row - 3 + j) * (2 * DI) + d], acc);
    }
    float v = acc / (1.f + __expf(-acc));   // silu
    xs[idx] = v;
    store_hl(xhi, xlo, idx, v);
}

// ---------------------------------------------------------------------------
// selective scan: thread per (subject, d). Fused softplus/recurrence/gate.
// ---------------------------------------------------------------------------
__global__ __launch_bounds__(128) void k_scan(
    const float* __restrict__ dtp, const float* __restrict__ xs,
    const float* __restrict__ dbl, const float* __restrict__ xz,
    __nv_bfloat16* __restrict__ yhi, __nv_bfloat16* __restrict__ ylo,
    const float* __restrict__ dtb, const float* __restrict__ alog,
    const float* __restrict__ Dp) {
    int s = blockIdx.x / (DI / 128);
    int d = (blockIdx.x % (DI / 128)) * 128 + threadIdx.x;
    int off = c_off[s], len = c_len[s];

    float a[DS], st[DS];
#pragma unroll
    for (int n = 0; n < DS; n++) {
        a[n] = -expf(alog[d * DS + n]);
        st[n] = 0.f;
    }
    float bias = dtb[d], Dd = Dp[d];

    for (int t = 0; t < len; t++) {
        int row = off + t;
        float dtr = dtp[(size_t)row * DI + d] + bias;
        float dt = (dtr > 20.f) ? dtr : log1pf(__expf(dtr));
        float xt = xs[(size_t)row * DI + d];
        const float4* bc = (const float4*)(dbl + (size_t)row * 80 + DTRANK);
        float Bv[DS], Cv[DS];
        *(float4*)&Bv[0]  = bc[0]; *(float4*)&Bv[4]  = bc[1];
        *(float4*)&Bv[8]  = bc[2]; *(float4*)&Bv[12] = bc[3];
        *(float4*)&Cv[0]  = bc[4]; *(float4*)&Cv[4]  = bc[5];
        *(float4*)&Cv[8]  = bc[6]; *(float4*)&Cv[12] = bc[7];
        float u = dt * xt;
        float y = 0.f;
#pragma unroll
        for (int n = 0; n < DS; n++) {
            float dA = __expf(dt * a[n]);
            st[n] = fmaf(dA, st[n], u * Bv[n]);
            y = fmaf(st[n], Cv[n], y);
        }
        float z = xz[(size_t)row * (2 * DI) + DI + d];
        float sig = 1.f / (1.f + __expf(-z));
        float val = (y + xt * Dd) * (z * sig);
        store_hl(yhi, ylo, (size_t)row * DI + d, val);
    }
}

// ---------------------------------------------------------------------------
// final: rmsnorm(norm_f_w) then rmsnorm(out_norm_w) -> d_out
// ---------------------------------------------------------------------------
__global__ void k_final(const float* __restrict__ h,
                        const float* __restrict__ wf,
                        const float* __restrict__ wo,
                        float* __restrict__ out) {
    int row  = blockIdx.x * 8 + (threadIdx.x >> 5);
    int lane = threadIdx.x & 31;
    if (row >= TOTAL) return;
    const float4* p   = (const float4*)(h + (size_t)row * DM);
    const float4* wf4 = (const float4*)wf;
    const float4* wo4 = (const float4*)wo;
    float4 v[6];
    float ss = 0.f;
#pragma unroll
    for (int i = 0; i < 6; i++) {
        v[i] = p[lane + 32 * i];
        ss += v[i].x * v[i].x + v[i].y * v[i].y + v[i].z * v[i].z + v[i].w * v[i].w;
    }
    ss = warp_sum(ss);
    float r1 = rsqrtf(ss * (1.f / DM) + EPS);
    float ss2 = 0.f;
#pragma unroll
    for (int i = 0; i < 6; i++) {
        float4 wv = wf4[lane + 32 * i];
        v[i].x *= r1 * wv.x; v[i].y *= r1 * wv.y;
        v[i].z *= r1 * wv.z; v[i].w *= r1 * wv.w;
        ss2 += v[i].x * v[i].x + v[i].y * v[i].y + v[i].z * v[i].z + v[i].w * v[i].w;
    }
    ss2 = warp_sum(ss2);
    float r2 = rsqrtf(ss2 * (1.f / DM) + EPS);
    float4* o4 = (float4*)(out + (size_t)row * DM);
#pragma unroll
    for (int i = 0; i < 6; i++) {
        float4 wv = wo4[lane + 32 * i];
        float4 t;
        t.x = v[i].x * r2 * wv.x; t.y = v[i].y * r2 * wv.y;
        t.z = v[i].z * r2 * wv.z; t.w = v[i].w * r2 * wv.w;
        o4[lane + 32 * i] = t;
    }
}

// ---------------------------------------------------------------------------
extern "C" void kernel_launch(void* const* d_in, const int* in_sizes, int n_in,
                              void* d_out, int out_size) {
    const int*   tokens     = (const int*)d_in[0];
    const float* embed      = (const float*)d_in[1];
    const float* in_norm_w  = (const float*)d_in[2];
    const float* out_norm_w = (const float*)d_in[3];
    const float* norm_w     = (const float*)d_in[4];
    const float* in_proj_w  = (const float*)d_in[5];
    const float* conv_w     = (const float*)d_in[6];
    const float* conv_b     = (const float*)d_in[7];
    const float* x_proj_w   = (const float*)d_in[8];
    const float* dt_proj_w  = (const float*)d_in[9];
    const float* dt_proj_b  = (const float*)d_in[10];
    const float* A_log      = (const float*)d_in[11];
    const float* D_param    = (const float*)d_in[12];
    const float* out_proj_w = (const float*)d_in[13];
    const float* norm_f_w   = (const float*)d_in[14];
    float* out = (float*)d_out;

    float *p_x, *p_xz, *p_xs, *p_dbl, *p_dtp;
    __nv_bfloat16 *p_hnh, *p_hnl, *p_xsh, *p_xsl, *p_dbh, *p_dbLo, *p_yh, *p_yl, *p_wh, *p_wl;
    cudaGetSymbolAddress((void**)&p_x,    g_x);
    cudaGetSymbolAddress((void**)&p_xz,   g_xz);
    cudaGetSymbolAddress((void**)&p_xs,   g_xs);
    cudaGetSymbolAddress((void**)&p_dbl,  g_dbl);
    cudaGetSymbolAddress((void**)&p_dtp,  g_dtp);
    cudaGetSymbolAddress((void**)&p_hnh,  g_hn_hi);
    cudaGetSymbolAddress((void**)&p_hnl,  g_hn_lo);
    cudaGetSymbolAddress((void**)&p_xsh,  g_xs_hi);
    cudaGetSymbolAddress((void**)&p_xsl,  g_xs_lo);
    cudaGetSymbolAddress((void**)&p_dbh,  g_db_hi);
    cudaGetSymbolAddress((void**)&p_dbLo, g_db_lo);
    cudaGetSymbolAddress((void**)&p_yh,   g_y_hi);
    cudaGetSymbolAddress((void**)&p_yl,   g_y_lo);
    cudaGetSymbolAddress((void**)&p_wh,   g_w_hi);
    cudaGetSymbolAddress((void**)&p_wl,   g_w_lo);

    const int rowBlocks = (TOTAL + 7) / 8;
    const int gy = (TOTAL + 127) / 128;   // 54

    k_embed<<<rowBlocks, 256>>>(tokens, embed, in_norm_w, p_x);

    for (int l = 0; l < 2; l++) {
        const float* ipw  = in_proj_w  + (size_t)l * 2 * DI * DM;
        const float* cw   = conv_w     + (size_t)l * DI * 4;
        const float* cb   = conv_b     + (size_t)l * DI;
        const float* xpw  = x_proj_w   + (size_t)l * 80 * DI;
        const float* dpw  = dt_proj_w  + (size_t)l * DI * DTRANK;
        const float* dpb  = dt_proj_b  + (size_t)l * DI;
        const float* al   = A_log      + (size_t)l * DI * DS;
        const float* Dpar = D_param    + (size_t)l * DI;
        const float* opw  = out_proj_w + (size_t)l * DM * DI;

        // hn = rmsnorm(h) -> bf16 hi/lo
        k_rmsnorm_split<<<rowBlocks, 256>>>(p_x, norm_w + (size_t)l * DM, p_hnh, p_hnl);

        // xz = hn @ in_proj^T : [TOTAL, 3072]
        k_split<<<(2 * DI * DM + 255) / 256, 256>>>(ipw, p_wh, p_wl, 2 * DI, DM, DM, DM);
        k_gemm<<<dim3(2 * DI / 128, gy), 256>>>(
            p_hnh, p_hnl, p_wh, p_wl, p_xz, TOTAL, 2 * DI, DM, 2 * DI, 0);

        // xs = silu(conv(x)+b) -> fp32 + bf16 hi/lo
        k_conv<<<(TOTAL * DI + 255) / 256, 256>>>(p_xz, cw, cb, p_xs, p_xsh, p_xsl);

        // dbl = xs @ x_proj^T : [TOTAL, 80]
        k_split<<<(80 * DI + 255) / 256, 256>>>(xpw, p_wh, p_wl, 80, DI, DI, DI);
        k_gemm<<<dim3(1, gy), 256>>>(
            p_xsh, p_xsl, p_wh, p_wl, p_dbl, TOTAL, 80, DI, 80, 0);

        // dtp = dbl[:, :48] @ dt_proj^T : [TOTAL, 1536]   (Kpad=64)
        k_split<<<(TOTAL * 64 + 255) / 256, 256>>>(p_dbl, p_dbh, p_dbLo, TOTAL, 48, 64, 80);
        k_split<<<(DI * 64 + 255) / 256, 256>>>(dpw, p_wh, p_wl, DI, 48, 64, 48);
        k_gemm<<<dim3(DI / 128, gy), 256>>>(
            p_dbh, p_dbLo, p_wh, p_wl, p_dtp, TOTAL, DI, 64, DI, 0);

        // selective scan -> y bf16 hi/lo
        k_scan<<<NSUBJ * (DI / 128), 128>>>(p_dtp, p_xs, p_dbl, p_xz,
                                            p_yh, p_yl, dpb, al, Dpar);

        // h += y @ out_proj^T : [TOTAL, 768]
        k_split<<<(DM * DI + 255) / 256, 256>>>(opw, p_wh, p_wl, DM, DI, DI, DI);
        k_gemm<<<dim3(DM / 128, gy), 256>>>(
            p_yh, p_yl, p_wh, p_wl, p_x, TOTAL, DM, DI, DM, 1);
    }

    k_final<<<rowBlocks, 256>>>(p_x, norm_f_w, out_norm_w, out);
}

// round 4
// speedup vs baseline: 2.0538x; 1.2133x over previous
#include <cuda_runtime.h>
#include <cuda_bf16.h>
#include <cstdint>
#include <math.h>

// ---------------------------------------------------------------------------
// FEMRMamba: 2-layer Mamba over 8 ragged subjects, compact [6848] layout.
// GEMMs: warp-level HMMA bf16 (fp32 acc), hi/lo split PASS-FUSED in mainloop.
// ---------------------------------------------------------------------------

#define TOTAL   6848
#define DM      768
#define DI      1536
#define DS      16
#define DTRANK  48
#define NSUBJ   8
#define EPS     1e-5f

__constant__ int c_off[NSUBJ] = {0, 1024, 1920, 2688, 3712, 4224, 4864, 5824};
__constant__ int c_len[NSUBJ] = {1024, 896, 768, 1024, 512, 640, 960, 1024};

// ---------------- scratch (device globals: allocation-free rule) -----------
__device__ float g_x  [TOTAL * DM];
__device__ float g_xz [TOTAL * 2 * DI];
__device__ float g_xs [TOTAL * DI];
__device__ float g_dbl[TOTAL * 80];
__device__ float g_dblp[4 * TOTAL * 80];   // split-K partials
__device__ float g_dtp[TOTAL * DI];

__device__ __nv_bfloat16 g_hn_hi[TOTAL * DM],  g_hn_lo[TOTAL * DM];
__device__ __nv_bfloat16 g_xs_hi[TOTAL * DI],  g_xs_lo[TOTAL * DI];
__device__ __nv_bfloat16 g_db_hi[TOTAL * 64],  g_db_lo[TOTAL * 64];
__device__ __nv_bfloat16 g_y_hi [TOTAL * DI],  g_y_lo [TOTAL * DI];
__device__ __nv_bfloat16 g_w_hi [2 * DI * DM], g_w_lo [2 * DI * DM];

// ---------------------------------------------------------------------------
__device__ __forceinline__ float warp_sum(float v) {
#pragma unroll
    for (int o = 16; o > 0; o >>= 1) v += __shfl_xor_sync(0xffffffffu, v, o);
    return v;
}
__device__ __forceinline__ void store_hl(__nv_bfloat16* hi, __nv_bfloat16* lo,
                                         size_t idx, float v) {
    __nv_bfloat16 h = __float2bfloat16(v);
    hi[idx] = h;
    lo[idx] = __float2bfloat16(v - __bfloat162float(h));
}
__device__ __forceinline__ uint32_t smem_u32(const void* p) {
    uint32_t a;
    asm("{ .reg .u64 t; cvta.to.shared.u64 t, %1; cvt.u32.u64 %0, t; }"
        : "=r"(a) : "l"(p));
    return a;
}
__device__ __forceinline__ void cp16(uint32_t dst, const void* src, int srcSize) {
    asm volatile("cp.async.cg.shared.global [%0], [%1], 16, %2;"
                 :: "r"(dst), "l"(src), "r"(srcSize) : "memory");
}
__device__ __forceinline__ void ldsm4(uint32_t& r0, uint32_t& r1, uint32_t& r2,
                                      uint32_t& r3, uint32_t addr) {
    asm volatile("ldmatrix.sync.aligned.m8n8.x4.shared.b16 {%0,%1,%2,%3}, [%4];"
                 : "=r"(r0), "=r"(r1), "=r"(r2), "=r"(r3) : "r"(addr));
}
__device__ __forceinline__ void mma16816(float* c, const uint32_t* a,
                                         const uint32_t* b) {
    asm volatile("mma.sync.aligned.m16n8k16.row.col.f32.bf16.bf16.f32 "
                 "{%0,%1,%2,%3}, {%4,%5,%6,%7}, {%8,%9}, {%0,%1,%2,%3};"
                 : "+f"(c[0]), "+f"(c[1]), "+f"(c[2]), "+f"(c[3])
                 : "r"(a[0]), "r"(a[1]), "r"(a[2]), "r"(a[3]),
                   "r"(b[0]), "r"(b[1]));
}

// ---------------------------------------------------------------------------
__global__ void k_embed(const int* __restrict__ tokens,
                        const float* __restrict__ embed,
                        const float* __restrict__ w,
                        float* __restrict__ out) {
    int row  = blockIdx.x * 8 + (threadIdx.x >> 5);
    int lane = threadIdx.x & 31;
    if (row >= TOTAL) return;
    int tok = tokens[row];
    const float4* e  = (const float4*)(embed + (size_t)tok * DM);
    const float4* w4 = (const float4*)w;
    float4 v[6];
    float ss = 0.f;
#pragma unroll
    for (int i = 0; i < 6; i++) {
        v[i] = e[lane + 32 * i];
        ss += v[i].x * v[i].x + v[i].y * v[i].y + v[i].z * v[i].z + v[i].w * v[i].w;
    }
    ss = warp_sum(ss);
    float r = rsqrtf(ss * (1.f / DM) + EPS);
    float4* o4 = (float4*)(out + (size_t)row * DM);
#pragma unroll
    for (int i = 0; i < 6; i++) {
        float4 wv = w4[lane + 32 * i];
        float4 t;
        t.x = v[i].x * r * wv.x; t.y = v[i].y * r * wv.y;
        t.z = v[i].z * r * wv.z; t.w = v[i].w * r * wv.w;
        o4[lane + 32 * i] = t;
    }
}

// ---------------------------------------------------------------------------
__global__ void k_rmsnorm_split(const float* __restrict__ in,
                                const float* __restrict__ w,
                                __nv_bfloat16* __restrict__ hi,
                                __nv_bfloat16* __restrict__ lo) {
    int row  = blockIdx.x * 8 + (threadIdx.x >> 5);
    int lane = threadIdx.x & 31;
    if (row >= TOTAL) return;
    const float4* p  = (const float4*)(in + (size_t)row * DM);
    const float4* w4 = (const float4*)w;
    float4 v[6];
    float ss = 0.f;
#pragma unroll
    for (int i = 0; i < 6; i++) {
        v[i] = p[lane + 32 * i];
        ss += v[i].x * v[i].x + v[i].y * v[i].y + v[i].z * v[i].z + v[i].w * v[i].w;
    }
    ss = warp_sum(ss);
    float r = rsqrtf(ss * (1.f / DM) + EPS);
    size_t base = (size_t)row * DM;
#pragma unroll
    for (int i = 0; i < 6; i++) {
        float4 wv = w4[lane + 32 * i];
        size_t c = base + (lane + 32 * i) * 4;
        store_hl(hi, lo, c + 0, v[i].x * r * wv.x);
        store_hl(hi, lo, c + 1, v[i].y * r * wv.y);
        store_hl(hi, lo, c + 2, v[i].z * r * wv.z);
        store_hl(hi, lo, c + 3, v[i].w * r * wv.w);
    }
}

// ---------------------------------------------------------------------------
__global__ void k_split(const float* __restrict__ src,
                        __nv_bfloat16* __restrict__ hi,
                        __nv_bfloat16* __restrict__ lo,
                        int rows, int K, int Kpad, int srcLd) {
    int idx = blockIdx.x * blockDim.x + threadIdx.x;
    if (idx >= rows * Kpad) return;
    int r = idx / Kpad, c = idx - r * Kpad;
    float v = (c < K) ? src[(size_t)r * srcLd + c] : 0.f;
    store_hl(hi, lo, idx, v);
}

// ---------------------------------------------------------------------------
// Pass-fused hi/lo HMMA GEMM-NT: C[m,n] = sum_k A[m,k]*B[n,k] with
// AhiBhi + AhiBlo + AloBhi accumulated in one K-sweep.
// Block 128x128, BK=32, 256 thr, warp tile 32x64, 2-stage cp.async.
// grid.z = splitk (partials written to C + z*zStride; addRes must be 0).
// ---------------------------------------------------------------------------
#define BK 32
#define LDS_ROW 40                       // halves per smem row (80B)
#define TILE_B  (128 * LDS_ROW * 2)      // bytes per tile
#define STAGE_B (4 * TILE_B)             // Ahi,Alo,Bhi,Blo
#define GEMM_SMEM (2 * STAGE_B)          // 81920 bytes

__global__ __launch_bounds__(256, 1) void k_gemm(
    const __nv_bfloat16* __restrict__ Ahi, const __nv_bfloat16* __restrict__ Alo,
    const __nv_bfloat16* __restrict__ Bhi, const __nv_bfloat16* __restrict__ Blo,
    float* __restrict__ C, int M, int N, int Kpad, int ldc, int addRes,
    int splitk, size_t zStride) {
    extern __shared__ char smem[];
    const uint32_t sBase = smem_u32(smem);

    const int tid = threadIdx.x;
    const int bm = blockIdx.y * 128, bn = blockIdx.x * 128;
    const int wid = tid >> 5, lane = tid & 31;
    const int wm = wid & 3, wn = wid >> 2;

    const int nchTot = Kpad / BK;
    const int per = nchTot / splitk;
    const int kStart = blockIdx.z * per * BK;
    if (splitk > 1) C += blockIdx.z * zStride;

    float acc[2][8][4];
#pragma unroll
    for (int i = 0; i < 2; i++)
#pragma unroll
        for (int j = 0; j < 8; j++)
#pragma unroll
            for (int q = 0; q < 4; q++) acc[i][j][q] = 0.f;

    // loader: 2 threads per row; each thread does 2x16B per tile (4 tiles)
    const int lrow = tid & 127;
    const int hcol = (tid >> 7) * 16;           // half-offset 0 or 16
    const int okA = (bm + lrow) < M ? 16 : 0;
    const int okB = (bn + lrow) < N ? 16 : 0;
    const size_t gA = (size_t)(bm + lrow) * Kpad + hcol;
    const size_t gB = (size_t)(bn + lrow) * Kpad + hcol;
    const uint32_t sOff = (uint32_t)(lrow * LDS_ROW + hcol) * 2;

#define LOAD_STAGE(it, buf) do {                                               \
    int _kc = kStart + (it) * BK;                                              \
    uint32_t _d = sBase + (buf) * STAGE_B + sOff;                              \
    const __nv_bfloat16* _p;                                                   \
    _p = Ahi + gA + _kc; cp16(_d, _p, okA); cp16(_d + 16, _p + 8, okA);        \
    _d += TILE_B;                                                              \
    _p = Alo + gA + _kc; cp16(_d, _p, okA); cp16(_d + 16, _p + 8, okA);        \
    _d += TILE_B;                                                              \
    _p = Bhi + gB + _kc; cp16(_d, _p, okB); cp16(_d + 16, _p + 8, okB);        \
    _d += TILE_B;                                                              \
    _p = Blo + gB + _kc; cp16(_d, _p, okB); cp16(_d + 16, _p + 8, okB);        \
    asm volatile("cp.async.commit_group;" ::: "memory");                       \
} while (0)

    LOAD_STAGE(0, 0);

    const int aRow0 = wm * 32 + (lane & 15);
    const int bRow0 = wn * 64 + ((lane >> 4) << 3) + (lane & 7);
    const int bCol0 = ((lane >> 3) & 1) << 3;
    const int aCol0 = (lane >> 4) << 3;

    for (int it = 0; it < per; ++it) {
        int buf = it & 1;
        if (it + 1 < per) {
            LOAD_STAGE(it + 1, buf ^ 1);
            asm volatile("cp.async.wait_group 1;" ::: "memory");
        } else {
            asm volatile("cp.async.wait_group 0;" ::: "memory");
        }
        __syncthreads();

        const uint32_t pAhi = sBase + buf * STAGE_B;
        const uint32_t pAlo = pAhi + TILE_B;
        const uint32_t pBhi = pAlo + TILE_B;
        const uint32_t pBlo = pBhi + TILE_B;

#pragma unroll
        for (int k16 = 0; k16 < 2; ++k16) {
            const int ac = k16 * 16 + aCol0;
            const int bc = k16 * 16 + bCol0;
            uint32_t ahi[2][4], alo[2][4];
#pragma unroll
            for (int mt = 0; mt < 2; ++mt) {
                uint32_t off = (uint32_t)((aRow0 + mt * 16) * LDS_ROW + ac) * 2;
                ldsm4(ahi[mt][0], ahi[mt][1], ahi[mt][2], ahi[mt][3], pAhi + off);
                ldsm4(alo[mt][0], alo[mt][1], alo[mt][2], alo[mt][3], pAlo + off);
            }
            uint32_t bhi[4][4], blo[4][4];
#pragma unroll
            for (int g = 0; g < 4; ++g) {
                uint32_t off = (uint32_t)((bRow0 + g * 16) * LDS_ROW + bc) * 2;
                ldsm4(bhi[g][0], bhi[g][1], bhi[g][2], bhi[g][3], pBhi + off);
                ldsm4(blo[g][0], blo[g][1], blo[g][2], blo[g][3], pBlo + off);
            }
#pragma unroll
            for (int mt = 0; mt < 2; ++mt)
#pragma unroll
                for (int g = 0; g < 4; ++g) {
                    mma16816(acc[mt][2 * g],     ahi[mt], &bhi[g][0]);
                    mma16816(acc[mt][2 * g + 1], ahi[mt], &bhi[g][2]);
                    mma16816(acc[mt][2 * g],     ahi[mt], &blo[g][0]);
                    mma16816(acc[mt][2 * g + 1], ahi[mt], &blo[g][2]);
                    mma16816(acc[mt][2 * g],     alo[mt], &bhi[g][0]);
                    mma16816(acc[mt][2 * g + 1], alo[mt], &bhi[g][2]);
                }
        }
        __syncthreads();
    }

    // epilogue
#pragma unroll
    for (int mt = 0; mt < 2; ++mt) {
#pragma unroll
        for (int h = 0; h < 2; ++h) {
            int m = bm + wm * 32 + mt * 16 + (lane >> 2) + h * 8;
            if (m >= M) continue;
#pragma unroll
            for (int nt = 0; nt < 8; ++nt) {
                int n = bn + wn * 64 + nt * 8 + (lane & 3) * 2;
                if (n < N) {
                    float2 v = make_float2(acc[mt][nt][2 * h], acc[mt][nt][2 * h + 1]);
                    float* cp = C + (size_t)m * ldc + n;
                    if (addRes) { float2 o = *(float2*)cp; v.x += o.x; v.y += o.y; }
                    *(float2*)cp = v;
                }
            }
        }
    }
#undef LOAD_STAGE
}

// ---------------------------------------------------------------------------
// reduce 4 split-K partials -> dbl
// ---------------------------------------------------------------------------
__global__ void k_reduce4(const float* __restrict__ p, float* __restrict__ out) {
    int idx = blockIdx.x * blockDim.x + threadIdx.x;
    if (idx >= TOTAL * 80) return;
    const size_t s = (size_t)TOTAL * 80;
    out[idx] = (p[idx] + p[idx + s]) + (p[idx + 2 * s] + p[idx + 3 * s]);
}

// ---------------------------------------------------------------------------
__global__ void k_conv(const float* __restrict__ xz,
                       const float* __restrict__ cw,
                       const float* __restrict__ cb,
                       float* __restrict__ xs,
                       __nv_bfloat16* __restrict__ xhi,
                       __nv_bfloat16* __restrict__ xlo) {
    int idx = blockIdx.x * blockDim.x + threadIdx.x;
    if (idx >= TOTAL * DI) return;
    int row = idx / DI;
    int d = idx - row * DI;
    int b = 0;
#pragma unroll
    for (int i = 1; i < NSUBJ; i++) if (row >= c_off[i]) b = i;
    int l = row - c_off[b];
    float acc = cb[d];
#pragma unroll
    for (int j = 0; j < 4; j++) {
        int ll = l - 3 + j;
        if (ll >= 0)
            acc = fmaf(cw[d * 4 + j], xz[(size_t)(row - 3 + j) * (2 * DI) + d], acc);
    }
    float v = acc / (1.f + __expf(-acc));
    xs[idx] = v;
    store_hl(xhi, xlo, idx, v);
}

// ---------------------------------------------------------------------------
__global__ __launch_bounds__(128) void k_scan(
    const float* __restrict__ dtp, const float* __restrict__ xs,
    const float* __restrict__ dbl, const float* __restrict__ xz,
    __nv_bfloat16* __restrict__ yhi, __nv_bfloat16* __restrict__ ylo,
    const float* __restrict__ dtb, const float* __restrict__ alog,
    const float* __restrict__ Dp) {
    int s = blockIdx.x / (DI / 128);
    int d = (blockIdx.x % (DI / 128)) * 128 + threadIdx.x;
    int off = c_off[s], len = c_len[s];

    float a[DS], st[DS];
#pragma unroll
    for (int n = 0; n < DS; n++) {
        a[n] = -expf(alog[d * DS + n]);
        st[n] = 0.f;
    }
    float bias = dtb[d], Dd = Dp[d];

    for (int t = 0; t < len; t++) {
        int row = off + t;
        float dtr = dtp[(size_t)row * DI + d] + bias;
        float dt = (dtr > 20.f) ? dtr : log1pf(__expf(dtr));
        float xt = xs[(size_t)row * DI + d];
        const float4* bc = (const float4*)(dbl + (size_t)row * 80 + DTRANK);
        float Bv[DS], Cv[DS];
        *(float4*)&Bv[0]  = bc[0]; *(float4*)&Bv[4]  = bc[1];
        *(float4*)&Bv[8]  = bc[2]; *(float4*)&Bv[12] = bc[3];
        *(float4*)&Cv[0]  = bc[4]; *(float4*)&Cv[4]  = bc[5];
        *(float4*)&Cv[8]  = bc[6]; *(float4*)&Cv[12] = bc[7];
        float u = dt * xt;
        float y = 0.f;
#pragma unroll
        for (int n = 0; n < DS; n++) {
            float dA = __expf(dt * a[n]);
            st[n] = fmaf(dA, st[n], u * Bv[n]);
            y = fmaf(st[n], Cv[n], y);
        }
        float z = xz[(size_t)row * (2 * DI) + DI + d];
        float sig = 1.f / (1.f + __expf(-z));
        float val = (y + xt * Dd) * (z * sig);
        store_hl(yhi, ylo, (size_t)row * DI + d, val);
    }
}

// ---------------------------------------------------------------------------
__global__ void k_final(const float* __restrict__ h,
                        const float* __restrict__ wf,
                        const float* __restrict__ wo,
                        float* __restrict__ out) {
    int row  = blockIdx.x * 8 + (threadIdx.x >> 5);
    int lane = threadIdx.x & 31;
    if (row >= TOTAL) return;
    const float4* p   = (const float4*)(h + (size_t)row * DM);
    const float4* wf4 = (const float4*)wf;
    const float4* wo4 = (const float4*)wo;
    float4 v[6];
    float ss = 0.f;
#pragma unroll
    for (int i = 0; i < 6; i++) {
        v[i] = p[lane + 32 * i];
        ss += v[i].x * v[i].x + v[i].y * v[i].y + v[i].z * v[i].z + v[i].w * v[i].w;
    }
    ss = warp_sum(ss);
    float r1 = rsqrtf(ss * (1.f / DM) + EPS);
    float ss2 = 0.f;
#pragma unroll
    for (int i = 0; i < 6; i++) {
        float4 wv = wf4[lane + 32 * i];
        v[i].x *= r1 * wv.x; v[i].y *= r1 * wv.y;
        v[i].z *= r1 * wv.z; v[i].w *= r1 * wv.w;
        ss2 += v[i].x * v[i].x + v[i].y * v[i].y + v[i].z * v[i].z + v[i].w * v[i].w;
    }
    ss2 = warp_sum(ss2);
    float r2 = rsqrtf(ss2 * (1.f / DM) + EPS);
    float4* o4 = (float4*)(out + (size_t)row * DM);
#pragma unroll
    for (int i = 0; i < 6; i++) {
        float4 wv = wo4[lane + 32 * i];
        float4 t;
        t.x = v[i].x * r2 * wv.x; t.y = v[i].y * r2 * wv.y;
        t.z = v[i].z * r2 * wv.z; t.w = v[i].w * r2 * wv.w;
        o4[lane + 32 * i] = t;
    }
}

// ---------------------------------------------------------------------------
extern "C" void kernel_launch(void* const* d_in, const int* in_sizes, int n_in,
                              void* d_out, int out_size) {
    const int*   tokens     = (const int*)d_in[0];
    const float* embed      = (const float*)d_in[1];
    const float* in_norm_w  = (const float*)d_in[2];
    const float* out_norm_w = (const float*)d_in[3];
    const float* norm_w     = (const float*)d_in[4];
    const float* in_proj_w  = (const float*)d_in[5];
    const float* conv_w     = (const float*)d_in[6];
    const float* conv_b     = (const float*)d_in[7];
    const float* x_proj_w   = (const float*)d_in[8];
    const float* dt_proj_w  = (const float*)d_in[9];
    const float* dt_proj_b  = (const float*)d_in[10];
    const float* A_log      = (const float*)d_in[11];
    const float* D_param    = (const float*)d_in[12];
    const float* out_proj_w = (const float*)d_in[13];
    const float* norm_f_w   = (const float*)d_in[14];
    float* out = (float*)d_out;

    float *p_x, *p_xz, *p_xs, *p_dbl, *p_dblp, *p_dtp;
    __nv_bfloat16 *p_hnh, *p_hnl, *p_xsh, *p_xsl, *p_dbh, *p_dbLo, *p_yh, *p_yl, *p_wh, *p_wl;
    cudaGetSymbolAddress((void**)&p_x,    g_x);
    cudaGetSymbolAddress((void**)&p_xz,   g_xz);
    cudaGetSymbolAddress((void**)&p_xs,   g_xs);
    cudaGetSymbolAddress((void**)&p_dbl,  g_dbl);
    cudaGetSymbolAddress((void**)&p_dblp, g_dblp);
    cudaGetSymbolAddress((void**)&p_dtp,  g_dtp);
    cudaGetSymbolAddress((void**)&p_hnh,  g_hn_hi);
    cudaGetSymbolAddress((void**)&p_hnl,  g_hn_lo);
    cudaGetSymbolAddress((void**)&p_xsh,  g_xs_hi);
    cudaGetSymbolAddress((void**)&p_xsl,  g_xs_lo);
    cudaGetSymbolAddress((void**)&p_dbh,  g_db_hi);
    cudaGetSymbolAddress((void**)&p_dbLo, g_db_lo);
    cudaGetSymbolAddress((void**)&p_yh,   g_y_hi);
    cudaGetSymbolAddress((void**)&p_yl,   g_y_lo);
    cudaGetSymbolAddress((void**)&p_wh,   g_w_hi);
    cudaGetSymbolAddress((void**)&p_wl,   g_w_lo);

    cudaFuncSetAttribute(k_gemm, cudaFuncAttributeMaxDynamicSharedMemorySize, GEMM_SMEM);

    const int rowBlocks = (TOTAL + 7) / 8;
    const int gy = (TOTAL + 127) / 128;   // 54

    k_embed<<<rowBlocks, 256>>>(tokens, embed, in_norm_w, p_x);

    for (int l = 0; l < 2; l++) {
        const float* ipw  = in_proj_w  + (size_t)l * 2 * DI * DM;
        const float* cw   = conv_w     + (size_t)l * DI * 4;
        const float* cb   = conv_b     + (size_t)l * DI;
        const float* xpw  = x_proj_w   + (size_t)l * 80 * DI;
        const float* dpw  = dt_proj_w  + (size_t)l * DI * DTRANK;
        const float* dpb  = dt_proj_b  + (size_t)l * DI;
        const float* al   = A_log      + (size_t)l * DI * DS;
        const float* Dpar = D_param    + (size_t)l * DI;
        const float* opw  = out_proj_w + (size_t)l * DM * DI;

        // hn = rmsnorm(h) -> bf16 hi/lo
        k_rmsnorm_split<<<rowBlocks, 256>>>(p_x, norm_w + (size_t)l * DM, p_hnh, p_hnl);

        // xz = hn @ in_proj^T : [TOTAL, 3072]
        k_split<<<(2 * DI * DM + 255) / 256, 256>>>(ipw, p_wh, p_wl, 2 * DI, DM, DM, DM);
        k_gemm<<<dim3(2 * DI / 128, gy, 1), 256, GEMM_SMEM>>>(
            p_hnh, p_hnl, p_wh, p_wl, p_xz, TOTAL, 2 * DI, DM, 2 * DI, 0, 1, 0);

        // xs = silu(conv(x)+b)
        k_conv<<<(TOTAL * DI + 255) / 256, 256>>>(p_xz, cw, cb, p_xs, p_xsh, p_xsl);

        // dbl = xs @ x_proj^T : [TOTAL, 80]  (split-K 4, deterministic reduce)
        k_split<<<(80 * DI + 255) / 256, 256>>>(xpw, p_wh, p_wl, 80, DI, DI, DI);
        k_gemm<<<dim3(1, gy, 4), 256, GEMM_SMEM>>>(
            p_xsh, p_xsl, p_wh, p_wl, p_dblp, TOTAL, 80, DI, 80, 0, 4,
            (size_t)TOTAL * 80);
        k_reduce4<<<(TOTAL * 80 + 255) / 256, 256>>>(p_dblp, p_dbl);

        // dtp = dbl[:, :48] @ dt_proj^T : [TOTAL, 1536]  (Kpad=64)
        k_split<<<(TOTAL * 64 + 255) / 256, 256>>>(p_dbl, p_dbh, p_dbLo, TOTAL, 48, 64, 80);
        k_split<<<(DI * 64 + 255) / 256, 256>>>(dpw, p_wh, p_wl, DI, 48, 64, 48);
        k_gemm<<<dim3(DI / 128, gy, 1), 256, GEMM_SMEM>>>(
            p_dbh, p_dbLo, p_wh, p_wl, p_dtp, TOTAL, DI, 64, DI, 0, 1, 0);

        // selective scan -> y bf16 hi/lo
        k_scan<<<NSUBJ * (DI / 128), 128>>>(p_dtp, p_xs, p_dbl, p_xz,
                                            p_yh, p_yl, dpb, al, Dpar);

        // h += y @ out_proj^T : [TOTAL, 768]
        k_split<<<(DM * DI + 255) / 256, 256>>>(opw, p_wh, p_wl, DM, DI, DI, DI);
        k_gemm<<<dim3(DM / 128, gy, 1), 256, GEMM_SMEM>>>(
            p_yh, p_yl, p_wh, p_wl, p_x, TOTAL, DM, DI, DM, 1, 1, 0);
    }

    k_final<<<rowBlocks, 256>>>(p_x, norm_f_w, out_norm_w, out);
}

// round 5
// speedup vs baseline: 2.3894x; 1.1634x over previous
#include <cuda_runtime.h>
#include <cuda_bf16.h>
#include <cstdint>
#include <math.h>

// ---------------------------------------------------------------------------
// FEMRMamba: 2-layer Mamba over 8 ragged subjects, compact [6848] layout.
// GEMMs: HMMA bf16 hi/lo pass-fused, 512 thr, 3-stage cp.async pipeline.
// ---------------------------------------------------------------------------

#define TOTAL   6848
#define DM      768
#define DI      1536
#define DS      16
#define DTRANK  48
#define NSUBJ   8
#define EPS     1e-5f

__constant__ int c_off[NSUBJ] = {0, 1024, 1920, 2688, 3712, 4224, 4864, 5824};
__constant__ int c_len[NSUBJ] = {1024, 896, 768, 1024, 512, 640, 960, 1024};

// ---------------- scratch (device globals) ---------------------------------
__device__ float g_x  [TOTAL * DM];
__device__ float g_xz [TOTAL * 2 * DI];
__device__ float g_xs [TOTAL * DI];
__device__ float g_dbl[TOTAL * 80];
__device__ float g_dblp[4 * TOTAL * 80];
__device__ float g_dtp[TOTAL * DI];

__device__ __nv_bfloat16 g_hn_hi[TOTAL * DM],  g_hn_lo[TOTAL * DM];
__device__ __nv_bfloat16 g_xs_hi[TOTAL * DI],  g_xs_lo[TOTAL * DI];
__device__ __nv_bfloat16 g_db_hi[TOTAL * 64],  g_db_lo[TOTAL * 64];
__device__ __nv_bfloat16 g_y_hi [TOTAL * DI],  g_y_lo [TOTAL * DI];
__device__ __nv_bfloat16 g_w_hi [2 * DI * DM], g_w_lo [2 * DI * DM];

// ---------------------------------------------------------------------------
__device__ __forceinline__ float warp_sum(float v) {
#pragma unroll
    for (int o = 16; o > 0; o >>= 1) v += __shfl_xor_sync(0xffffffffu, v, o);
    return v;
}
__device__ __forceinline__ void store_hl(__nv_bfloat16* hi, __nv_bfloat16* lo,
                                         size_t idx, float v) {
    __nv_bfloat16 h = __float2bfloat16(v);
    hi[idx] = h;
    lo[idx] = __float2bfloat16(v - __bfloat162float(h));
}
__device__ __forceinline__ uint32_t smem_u32(const void* p) {
    uint32_t a;
    asm("{ .reg .u64 t; cvta.to.shared.u64 t, %1; cvt.u32.u64 %0, t; }"
        : "=r"(a) : "l"(p));
    return a;
}
__device__ __forceinline__ void cp16(uint32_t dst, const void* src, int srcSize) {
    asm volatile("cp.async.cg.shared.global [%0], [%1], 16, %2;"
                 :: "r"(dst), "l"(src), "r"(srcSize) : "memory");
}
__device__ __forceinline__ void ldsm4(uint32_t& r0, uint32_t& r1, uint32_t& r2,
                                      uint32_t& r3, uint32_t addr) {
    asm volatile("ldmatrix.sync.aligned.m8n8.x4.shared.b16 {%0,%1,%2,%3}, [%4];"
                 : "=r"(r0), "=r"(r1), "=r"(r2), "=r"(r3) : "r"(addr));
}
__device__ __forceinline__ void mma16816(float* c, const uint32_t* a,
                                         const uint32_t* b) {
    asm volatile("mma.sync.aligned.m16n8k16.row.col.f32.bf16.bf16.f32 "
                 "{%0,%1,%2,%3}, {%4,%5,%6,%7}, {%8,%9}, {%0,%1,%2,%3};"
                 : "+f"(c[0]), "+f"(c[1]), "+f"(c[2]), "+f"(c[3])
                 : "r"(a[0]), "r"(a[1]), "r"(a[2]), "r"(a[3]),
                   "r"(b[0]), "r"(b[1]));
}

// ---------------------------------------------------------------------------
__global__ void k_embed(const int* __restrict__ tokens,
                        const float* __restrict__ embed,
                        const float* __restrict__ w,
                        float* __restrict__ out) {
    int row  = blockIdx.x * 8 + (threadIdx.x >> 5);
    int lane = threadIdx.x & 31;
    if (row >= TOTAL) return;
    int tok = tokens[row];
    const float4* e  = (const float4*)(embed + (size_t)tok * DM);
    const float4* w4 = (const float4*)w;
    float4 v[6];
    float ss = 0.f;
#pragma unroll
    for (int i = 0; i < 6; i++) {
        v[i] = e[lane + 32 * i];
        ss += v[i].x * v[i].x + v[i].y * v[i].y + v[i].z * v[i].z + v[i].w * v[i].w;
    }
    ss = warp_sum(ss);
    float r = rsqrtf(ss * (1.f / DM) + EPS);
    float4* o4 = (float4*)(out + (size_t)row * DM);
#pragma unroll
    for (int i = 0; i < 6; i++) {
        float4 wv = w4[lane + 32 * i];
        float4 t;
        t.x = v[i].x * r * wv.x; t.y = v[i].y * r * wv.y;
        t.z = v[i].z * r * wv.z; t.w = v[i].w * r * wv.w;
        o4[lane + 32 * i] = t;
    }
}

// ---------------------------------------------------------------------------
__global__ void k_rmsnorm_split(const float* __restrict__ in,
                                const float* __restrict__ w,
                                __nv_bfloat16* __restrict__ hi,
                                __nv_bfloat16* __restrict__ lo) {
    int row  = blockIdx.x * 8 + (threadIdx.x >> 5);
    int lane = threadIdx.x & 31;
    if (row >= TOTAL) return;
    const float4* p  = (const float4*)(in + (size_t)row * DM);
    const float4* w4 = (const float4*)w;
    float4 v[6];
    float ss = 0.f;
#pragma unroll
    for (int i = 0; i < 6; i++) {
        v[i] = p[lane + 32 * i];
        ss += v[i].x * v[i].x + v[i].y * v[i].y + v[i].z * v[i].z + v[i].w * v[i].w;
    }
    ss = warp_sum(ss);
    float r = rsqrtf(ss * (1.f / DM) + EPS);
    size_t base = (size_t)row * DM;
#pragma unroll
    for (int i = 0; i < 6; i++) {
        float4 wv = w4[lane + 32 * i];
        size_t c = base + (lane + 32 * i) * 4;
        store_hl(hi, lo, c + 0, v[i].x * r * wv.x);
        store_hl(hi, lo, c + 1, v[i].y * r * wv.y);
        store_hl(hi, lo, c + 2, v[i].z * r * wv.z);
        store_hl(hi, lo, c + 3, v[i].w * r * wv.w);
    }
}

// ---------------------------------------------------------------------------
__global__ void k_split(const float* __restrict__ src,
                        __nv_bfloat16* __restrict__ hi,
                        __nv_bfloat16* __restrict__ lo,
                        int rows, int K, int Kpad, int srcLd) {
    int idx = blockIdx.x * blockDim.x + threadIdx.x;
    if (idx >= rows * Kpad) return;
    int r = idx / Kpad, c = idx - r * Kpad;
    float v = (c < K) ? src[(size_t)r * srcLd + c] : 0.f;
    store_hl(hi, lo, idx, v);
}

// ---------------------------------------------------------------------------
// Pass-fused hi/lo HMMA GEMM-NT, 512 threads, 16 warps (4x4), warp tile 32x32,
// BK=32, 3-stage cp.async pipeline. grid.z = splitk.
// ---------------------------------------------------------------------------
#define BK 32
#define LDS_ROW 40
#define TILE_B  (128 * LDS_ROW * 2)
#define STAGE_B (4 * TILE_B)
#define GEMM_SMEM (3 * STAGE_B)          // 122880

__global__ __launch_bounds__(512, 1) void k_gemm(
    const __nv_bfloat16* __restrict__ Ahi, const __nv_bfloat16* __restrict__ Alo,
    const __nv_bfloat16* __restrict__ Bhi, const __nv_bfloat16* __restrict__ Blo,
    float* __restrict__ C, int M, int N, int Kpad, int ldc, int addRes,
    int splitk, size_t zStride) {
    extern __shared__ char smem[];
    const uint32_t sBase = smem_u32(smem);

    const int tid = threadIdx.x;
    const int bm = blockIdx.y * 128, bn = blockIdx.x * 128;
    const int wid = tid >> 5, lane = tid & 31;
    const int wm = wid & 3, wn = wid >> 2;

    const int per = (Kpad / BK) / splitk;
    const int kStart = blockIdx.z * per * BK;
    if (splitk > 1) C += blockIdx.z * zStride;

    float acc[2][4][4];
#pragma unroll
    for (int i = 0; i < 2; i++)
#pragma unroll
        for (int j = 0; j < 4; j++)
#pragma unroll
            for (int q = 0; q < 4; q++) acc[i][j][q] = 0.f;

    // loader: 512 thr; each does 1x16B per tile (4 tiles)
    const int lrow = tid & 127;
    const int lc = tid >> 7;                    // 0..3 -> 16B chunk
    const int okA = (bm + lrow) < M ? 16 : 0;
    const int okB = (bn + lrow) < N ? 16 : 0;
    const size_t gA = (size_t)(bm + lrow) * Kpad + lc * 8;
    const size_t gB = (size_t)(bn + lrow) * Kpad + lc * 8;
    const uint32_t sOff = (uint32_t)(lrow * LDS_ROW) * 2 + lc * 16;

#define LOAD_STAGE(it, buf) do {                                               \
    int _kc = kStart + (it) * BK;                                              \
    uint32_t _d = sBase + (buf) * STAGE_B + sOff;                              \
    cp16(_d,              Ahi + gA + _kc, okA);                                \
    cp16(_d + TILE_B,     Alo + gA + _kc, okA);                                \
    cp16(_d + 2 * TILE_B, Bhi + gB + _kc, okB);                                \
    cp16(_d + 3 * TILE_B, Blo + gB + _kc, okB);                                \
    asm volatile("cp.async.commit_group;" ::: "memory");                       \
} while (0)

    LOAD_STAGE(0, 0);
    if (per > 1) LOAD_STAGE(1, 1);

    const int aRow0 = wm * 32 + (lane & 15);
    const int aCol0 = (lane >> 4) << 3;
    const int bRow0 = wn * 32 + ((lane >> 4) << 3) + (lane & 7);
    const int bCol0 = ((lane >> 3) & 1) << 3;

    for (int it = 0; it < per; ++it) {
        if (it < per - 1)
            asm volatile("cp.async.wait_group 1;" ::: "memory");
        else
            asm volatile("cp.async.wait_group 0;" ::: "memory");
        __syncthreads();
        if (it + 2 < per) LOAD_STAGE(it + 2, (it + 2) % 3);

        const uint32_t pAhi = sBase + (it % 3) * STAGE_B;
        const uint32_t pAlo = pAhi + TILE_B;
        const uint32_t pBhi = pAlo + TILE_B;
        const uint32_t pBlo = pBhi + TILE_B;

#pragma unroll
        for (int k16 = 0; k16 < 2; ++k16) {
            const int ac = k16 * 16 + aCol0;
            const int bc = k16 * 16 + bCol0;
            uint32_t ahi[2][4], alo[2][4];
#pragma unroll
            for (int mt = 0; mt < 2; ++mt) {
                uint32_t off = (uint32_t)((aRow0 + mt * 16) * LDS_ROW + ac) * 2;
                ldsm4(ahi[mt][0], ahi[mt][1], ahi[mt][2], ahi[mt][3], pAhi + off);
                ldsm4(alo[mt][0], alo[mt][1], alo[mt][2], alo[mt][3], pAlo + off);
            }
            uint32_t bhi[2][4], blo[2][4];
#pragma unroll
            for (int g = 0; g < 2; ++g) {
                uint32_t off = (uint32_t)((bRow0 + g * 16) * LDS_ROW + bc) * 2;
                ldsm4(bhi[g][0], bhi[g][1], bhi[g][2], bhi[g][3], pBhi + off);
                ldsm4(blo[g][0], blo[g][1], blo[g][2], blo[g][3], pBlo + off);
            }
#pragma unroll
            for (int mt = 0; mt < 2; ++mt)
#pragma unroll
                for (int g = 0; g < 2; ++g) {
                    mma16816(acc[mt][2 * g],     ahi[mt], &bhi[g][0]);
                    mma16816(acc[mt][2 * g + 1], ahi[mt], &bhi[g][2]);
                    mma16816(acc[mt][2 * g],     ahi[mt], &blo[g][0]);
                    mma16816(acc[mt][2 * g + 1], ahi[mt], &blo[g][2]);
                    mma16816(acc[mt][2 * g],     alo[mt], &bhi[g][0]);
                    mma16816(acc[mt][2 * g + 1], alo[mt], &bhi[g][2]);
                }
        }
    }

    // epilogue
#pragma unroll
    for (int mt = 0; mt < 2; ++mt) {
#pragma unroll
        for (int h = 0; h < 2; ++h) {
            int m = bm + wm * 32 + mt * 16 + (lane >> 2) + h * 8;
            if (m >= M) continue;
#pragma unroll
            for (int nt = 0; nt < 4; ++nt) {
                int n = bn + wn * 32 + nt * 8 + (lane & 3) * 2;
                if (n < N) {
                    float2 v = make_float2(acc[mt][nt][2 * h], acc[mt][nt][2 * h + 1]);
                    float* cp = C + (size_t)m * ldc + n;
                    if (addRes) { float2 o = *(float2*)cp; v.x += o.x; v.y += o.y; }
                    *(float2*)cp = v;
                }
            }
        }
    }
#undef LOAD_STAGE
}

// ---------------------------------------------------------------------------
// reduce 4 split-K partials -> dbl fp32, plus hi/lo split of dt slice (pad 64)
// ---------------------------------------------------------------------------
__global__ void k_reduce4(const float* __restrict__ p, float* __restrict__ out,
                          __nv_bfloat16* __restrict__ dbh,
                          __nv_bfloat16* __restrict__ dblo) {
    int idx = blockIdx.x * blockDim.x + threadIdx.x;
    if (idx >= TOTAL * 80) return;
    const size_t s = (size_t)TOTAL * 80;
    float v = (p[idx] + p[idx + s]) + (p[idx + 2 * s] + p[idx + 3 * s]);
    out[idx] = v;
    int row = idx / 80, col = idx - row * 80;
    if (col < 48) {
        store_hl(dbh, dblo, (size_t)row * 64 + col, v);
    } else if (col < 64) {
        dbh[(size_t)row * 64 + col] = __float2bfloat16(0.f);
        dblo[(size_t)row * 64 + col] = __float2bfloat16(0.f);
    }
}

// ---------------------------------------------------------------------------
__global__ void k_conv(const float* __restrict__ xz,
                       const float* __restrict__ cw,
                       const float* __restrict__ cb,
                       float* __restrict__ xs,
                       __nv_bfloat16* __restrict__ xhi,
                       __nv_bfloat16* __restrict__ xlo) {
    int idx = blockIdx.x * blockDim.x + threadIdx.x;
    if (idx >= TOTAL * DI) return;
    int row = idx / DI;
    int d = idx - row * DI;
    int b = 0;
#pragma unroll
    for (int i = 1; i < NSUBJ; i++) if (row >= c_off[i]) b = i;
    int l = row - c_off[b];
    float acc = cb[d];
#pragma unroll
    for (int j = 0; j < 4; j++) {
        int ll = l - 3 + j;
        if (ll >= 0)
            acc = fmaf(cw[d * 4 + j], xz[(size_t)(row - 3 + j) * (2 * DI) + d], acc);
    }
    float v = acc / (1.f + __expf(-acc));
    xs[idx] = v;
    store_hl(xhi, xlo, idx, v);
}

// ---------------------------------------------------------------------------
// selective scan. Fast path: A_log[d,n] = log(n+1) -> dA_n = exp(-dt)^(n+1),
// one MUFU exp + 15 multiplies; per-thread verified, generic fallback.
// ---------------------------------------------------------------------------
__global__ __launch_bounds__(128) void k_scan(
    const float* __restrict__ dtp, const float* __restrict__ xs,
    const float* __restrict__ dbl, const float* __restrict__ xz,
    __nv_bfloat16* __restrict__ yhi, __nv_bfloat16* __restrict__ ylo,
    const float* __restrict__ dtb, const float* __restrict__ alog,
    const float* __restrict__ Dp) {
    int s = blockIdx.x / (DI / 128);
    int d = (blockIdx.x % (DI / 128)) * 128 + threadIdx.x;
    int off = c_off[s], len = c_len[s];

    float a[DS], st[DS];
    bool fast = true;
#pragma unroll
    for (int n = 0; n < DS; n++) {
        a[n] = -expf(alog[d * DS + n]);
        st[n] = 0.f;
        fast &= (fabsf(a[n] + (float)(n + 1)) <= 1e-5f * (float)(n + 1));
    }
    float bias = dtb[d], Dd = Dp[d];

    if (fast) {
        for (int t = 0; t < len; t++) {
            int row = off + t;
            float dtr = dtp[(size_t)row * DI + d] + bias;
            float dt = (dtr > 20.f) ? dtr : log1pf(__expf(dtr));
            float xt = xs[(size_t)row * DI + d];
            const float4* bc = (const float4*)(dbl + (size_t)row * 80 + DTRANK);
            float Bv[DS], Cv[DS];
            *(float4*)&Bv[0]  = bc[0]; *(float4*)&Bv[4]  = bc[1];
            *(float4*)&Bv[8]  = bc[2]; *(float4*)&Bv[12] = bc[3];
            *(float4*)&Cv[0]  = bc[4]; *(float4*)&Cv[4]  = bc[5];
            *(float4*)&Cv[8]  = bc[6]; *(float4*)&Cv[12] = bc[7];
            float u = dt * xt;
            float p = __expf(-dt);
            float dA = 1.f;
            float y = 0.f;
#pragma unroll
            for (int n = 0; n < DS; n++) {
                dA *= p;                                   // p^(n+1)
                st[n] = fmaf(dA, st[n], u * Bv[n]);
                y = fmaf(st[n], Cv[n], y);
            }
            float z = xz[(size_t)row * (2 * DI) + DI + d];
            float sig = 1.f / (1.f + __expf(-z));
            float val = (y + xt * Dd) * (z * sig);
            store_hl(yhi, ylo, (size_t)row * DI + d, val);
        }
    } else {
        for (int t = 0; t < len; t++) {
            int row = off + t;
            float dtr = dtp[(size_t)row * DI + d] + bias;
            float dt = (dtr > 20.f) ? dtr : log1pf(__expf(dtr));
            float xt = xs[(size_t)row * DI + d];
            const float4* bc = (const float4*)(dbl + (size_t)row * 80 + DTRANK);
            float Bv[DS], Cv[DS];
            *(float4*)&Bv[0]  = bc[0]; *(float4*)&Bv[4]  = bc[1];
            *(float4*)&Bv[8]  = bc[2]; *(float4*)&Bv[12] = bc[3];
            *(float4*)&Cv[0]  = bc[4]; *(float4*)&Cv[4]  = bc[5];
            *(float4*)&Cv[8]  = bc[6]; *(float4*)&Cv[12] = bc[7];
            float u = dt * xt;
            float y = 0.f;
#pragma unroll
            for (int n = 0; n < DS; n++) {
                float dA = __expf(dt * a[n]);
                st[n] = fmaf(dA, st[n], u * Bv[n]);
                y = fmaf(st[n], Cv[n], y);
            }
            float z = xz[(size_t)row * (2 * DI) + DI + d];
            float sig = 1.f / (1.f + __expf(-z));
            float val = (y + xt * Dd) * (z * sig);
            store_hl(yhi, ylo, (size_t)row * DI + d, val);
        }
    }
}

// ---------------------------------------------------------------------------
__global__ void k_final(const float* __restrict__ h,
                        const float* __restrict__ wf,
                        const float* __restrict__ wo,
                        float* __restrict__ out) {
    int row  = blockIdx.x * 8 + (threadIdx.x >> 5);
    int lane = threadIdx.x & 31;
    if (row >= TOTAL) return;
    const float4* p   = (const float4*)(h + (size_t)row * DM);
    const float4* wf4 = (const float4*)wf;
    const float4* wo4 = (const float4*)wo;
    float4 v[6];
    float ss = 0.f;
#pragma unroll
    for (int i = 0; i < 6; i++) {
        v[i] = p[lane + 32 * i];
        ss += v[i].x * v[i].x + v[i].y * v[i].y + v[i].z * v[i].z + v[i].w * v[i].w;
    }
    ss = warp_sum(ss);
    float r1 = rsqrtf(ss * (1.f / DM) + EPS);
    float ss2 = 0.f;
#pragma unroll
    for (int i = 0; i < 6; i++) {
        float4 wv = wf4[lane + 32 * i];
        v[i].x *= r1 * wv.x; v[i].y *= r1 * wv.y;
        v[i].z *= r1 * wv.z; v[i].w *= r1 * wv.w;
        ss2 += v[i].x * v[i].x + v[i].y * v[i].y + v[i].z * v[i].z + v[i].w * v[i].w;
    }
    ss2 = warp_sum(ss2);
    float r2 = rsqrtf(ss2 * (1.f / DM) + EPS);
    float4* o4 = (float4*)(out + (size_t)row * DM);
#pragma unroll
    for (int i = 0; i < 6; i++) {
        float4 wv = wo4[lane + 32 * i];
        float4 t;
        t.x = v[i].x * r2 * wv.x; t.y = v[i].y * r2 * wv.y;
        t.z = v[i].z * r2 * wv.z; t.w = v[i].w * r2 * wv.w;
        o4[lane + 32 * i] = t;
    }
}

// ---------------------------------------------------------------------------
extern "C" void kernel_launch(void* const* d_in, const int* in_sizes, int n_in,
                              void* d_out, int out_size) {
    const int*   tokens     = (const int*)d_in[0];
    const float* embed      = (const float*)d_in[1];
    const float* in_norm_w  = (const float*)d_in[2];
    const float* out_norm_w = (const float*)d_in[3];
    const float* norm_w     = (const float*)d_in[4];
    const float* in_proj_w  = (const float*)d_in[5];
    const float* conv_w     = (const float*)d_in[6];
    const float* conv_b     = (const float*)d_in[7];
    const float* x_proj_w   = (const float*)d_in[8];
    const float* dt_proj_w  = (const float*)d_in[9];
    const float* dt_proj_b  = (const float*)d_in[10];
    const float* A_log      = (const float*)d_in[11];
    const float* D_param    = (const float*)d_in[12];
    const float* out_proj_w = (const float*)d_in[13];
    const float* norm_f_w   = (const float*)d_in[14];
    float* out = (float*)d_out;

    float *p_x, *p_xz, *p_xs, *p_dbl, *p_dblp, *p_dtp;
    __nv_bfloat16 *p_hnh, *p_hnl, *p_xsh, *p_xsl, *p_dbh, *p_dbLo, *p_yh, *p_yl, *p_wh, *p_wl;
    cudaGetSymbolAddress((void**)&p_x,    g_x);
    cudaGetSymbolAddress((void**)&p_xz,   g_xz);
    cudaGetSymbolAddress((void**)&p_xs,   g_xs);
    cudaGetSymbolAddress((void**)&p_dbl,  g_dbl);
    cudaGetSymbolAddress((void**)&p_dblp, g_dblp);
    cudaGetSymbolAddress((void**)&p_dtp,  g_dtp);
    cudaGetSymbolAddress((void**)&p_hnh,  g_hn_hi);
    cudaGetSymbolAddress((void**)&p_hnl,  g_hn_lo);
    cudaGetSymbolAddress((void**)&p_xsh,  g_xs_hi);
    cudaGetSymbolAddress((void**)&p_xsl,  g_xs_lo);
    cudaGetSymbolAddress((void**)&p_dbh,  g_db_hi);
    cudaGetSymbolAddress((void**)&p_dbLo, g_db_lo);
    cudaGetSymbolAddress((void**)&p_yh,   g_y_hi);
    cudaGetSymbolAddress((void**)&p_yl,   g_y_lo);
    cudaGetSymbolAddress((void**)&p_wh,   g_w_hi);
    cudaGetSymbolAddress((void**)&p_wl,   g_w_lo);

    cudaFuncSetAttribute(k_gemm, cudaFuncAttributeMaxDynamicSharedMemorySize, GEMM_SMEM);

    const int rowBlocks = (TOTAL + 7) / 8;
    const int gy = (TOTAL + 127) / 128;   // 54

    k_embed<<<rowBlocks, 256>>>(tokens, embed, in_norm_w, p_x);

    for (int l = 0; l < 2; l++) {
        const float* ipw  = in_proj_w  + (size_t)l * 2 * DI * DM;
        const float* cw   = conv_w     + (size_t)l * DI * 4;
        const float* cb   = conv_b     + (size_t)l * DI;
        const float* xpw  = x_proj_w   + (size_t)l * 80 * DI;
        const float* dpw  = dt_proj_w  + (size_t)l * DI * DTRANK;
        const float* dpb  = dt_proj_b  + (size_t)l * DI;
        const float* al   = A_log      + (size_t)l * DI * DS;
        const float* Dpar = D_param    + (size_t)l * DI;
        const float* opw  = out_proj_w + (size_t)l * DM * DI;

        // hn = rmsnorm(h) -> bf16 hi/lo
        k_rmsnorm_split<<<rowBlocks, 256>>>(p_x, norm_w + (size_t)l * DM, p_hnh, p_hnl);

        // xz = hn @ in_proj^T : [TOTAL, 3072]
        k_split<<<(2 * DI * DM + 255) / 256, 256>>>(ipw, p_wh, p_wl, 2 * DI, DM, DM, DM);
        k_gemm<<<dim3(2 * DI / 128, gy, 1), 512, GEMM_SMEM>>>(
            p_hnh, p_hnl, p_wh, p_wl, p_xz, TOTAL, 2 * DI, DM, 2 * DI, 0, 1, 0);

        // xs = silu(conv(x)+b)
        k_conv<<<(TOTAL * DI + 255) / 256, 256>>>(p_xz, cw, cb, p_xs, p_xsh, p_xsl);

        // dbl = xs @ x_proj^T : [TOTAL, 80]  (split-K 4, deterministic reduce)
        k_split<<<(80 * DI + 255) / 256, 256>>>(xpw, p_wh, p_wl, 80, DI, DI, DI);
        k_gemm<<<dim3(1, gy, 4), 512, GEMM_SMEM>>>(
            p_xsh, p_xsl, p_wh, p_wl, p_dblp, TOTAL, 80, DI, 80, 0, 4,
            (size_t)TOTAL * 80);
        k_reduce4<<<(TOTAL * 80 + 255) / 256, 256>>>(p_dblp, p_dbl, p_dbh, p_dbLo);

        // dtp = dbl[:, :48] @ dt_proj^T : [TOTAL, 1536]  (Kpad=64)
        k_split<<<(DI * 64 + 255) / 256, 256>>>(dpw, p_wh, p_wl, DI, 48, 64, 48);
        k_gemm<<<dim3(DI / 128, gy, 1), 512, GEMM_SMEM>>>(
            p_dbh, p_dbLo, p_wh, p_wl, p_dtp, TOTAL, DI, 64, DI, 0, 1, 0);

        // selective scan -> y bf16 hi/lo
        k_scan<<<NSUBJ * (DI / 128), 128>>>(p_dtp, p_xs, p_dbl, p_xz,
                                            p_yh, p_yl, dpb, al, Dpar);

        // h += y @ out_proj^T : [TOTAL, 768]
        k_split<<<(DM * DI + 255) / 256, 256>>>(opw, p_wh, p_wl, DM, DI, DI, DI);
        k_gemm<<<dim3(DM / 128, gy, 1), 512, GEMM_SMEM>>>(
            p_yh, p_yl, p_wh, p_wl, p_x, TOTAL, DM, DI, DM, 1, 1, 0);
    }

    k_final<<<rowBlocks, 256>>>(p_x, norm_f_w, out_norm_w, out);
}